// round 15
// baseline (speedup 1.0000x reference)
#include <cuda_runtime.h>
#include <cuda_fp16.h>
#include <cstdint>

#define N_NODES 50000
#define DIM     512
#define N_EDGES 1600000
#define H2ROW   (DIM / 2)
#define RED_BLOCKS 1024

// ---- scratch (no allocations allowed -> __device__ globals) ----
__device__ __half2 g_yh[N_NODES * DIM / 2];  // x @ W^T in fp16 (SpMM gather source)
__device__ __half2 g_xh[N_NODES * DIM / 2];  // X in fp16 (GEMM A + residual source)
__device__ __half2 g_y2h[N_NODES * DIM / 2]; // SpMM output in fp16
__device__ __half2 g_wh[DIM * DIM / 2];      // W in fp16 (GEMM B)
__device__ int   g_cnt[N_NODES];
__device__ int   g_start[N_NODES + 1];
__device__ int   g_cursor[N_NODES];
__device__ int2  g_edges[N_EDGES];           // packed (col, val_bits), row-sorted
__device__ float g_colsum[DIM];              // later overwritten with mu[]
__device__ float g_stats[2];                 // [0]=sum of squares, [1]=alpha
__device__ int   g_done;                     // last-block counter for fused finalize

// ---------------- CSR build ----------------
__global__ void k_hist(const int* __restrict__ rows) {
    int i = blockIdx.x * blockDim.x + threadIdx.x;
    if (i < N_EDGES) atomicAdd(&g_cnt[rows[i]], 1);
}

__global__ void k_scan() {
    __shared__ int sm[1024];
    int t = threadIdx.x;
    if (t < DIM) g_colsum[t] = 0.f;
    if (t == 0)  { g_stats[0] = 0.f; g_done = 0; }
    const int CH = (N_NODES + 1023) / 1024;
    int lo = t * CH;
    int hi = min(lo + CH, N_NODES);
    int sum = 0;
    for (int i = lo; i < hi; i++) sum += g_cnt[i];
    sm[t] = sum;
    __syncthreads();
    for (int off = 1; off < 1024; off <<= 1) {
        int v = (t >= off) ? sm[t - off] : 0;
        __syncthreads();
        sm[t] += v;
        __syncthreads();
    }
    int run = sm[t] - sum;
    for (int i = lo; i < hi; i++) {
        g_start[i]  = run;
        g_cursor[i] = run;
        run += g_cnt[i];
    }
    if (t == 1023) g_start[N_NODES] = sm[1023];
}

__global__ void k_scatter(const int* __restrict__ rows,
                          const int* __restrict__ cols,
                          const float* __restrict__ vals) {
    int i = blockIdx.x * blockDim.x + threadIdx.x;
    if (i < N_EDGES) {
        int r = rows[i];
        int p = atomicAdd(&g_cursor[r], 1);
        g_edges[p] = make_int2(cols[i], __float_as_int(vals[i]));
    }
}

// ---------------- fp32 -> fp16 conversion of X and W ----------------
#define NX4 (N_NODES * DIM / 4)
#define NW4 (DIM * DIM / 4)
__global__ __launch_bounds__(256) void k_cvt(const float* __restrict__ X,
                                             const float* __restrict__ W) {
    int i = blockIdx.x * blockDim.x + threadIdx.x;
    if (i < NX4) {
        float4 v = *(const float4*)&X[i * 4];
        g_xh[i * 2]     = __floats2half2_rn(v.x, v.y);
        g_xh[i * 2 + 1] = __floats2half2_rn(v.z, v.w);
    } else if (i < NX4 + NW4) {
        int j = i - NX4;
        float4 v = *(const float4*)&W[j * 4];
        g_wh[j * 2]     = __floats2half2_rn(v.x, v.y);
        g_wh[j * 2 + 1] = __floats2half2_rn(v.z, v.w);
    }
}

// ====== GEMM: g_yh = X @ W^T via mma.sync f16 + ldmatrix (2-stage, .ca) ======
#define BM 128
#define BN 128
#define PADH 40
#define AH_BYTES (128 * PADH * 2)
#define BUFH (2 * AH_BYTES)
#define GEMM_SMEM (2 * BUFH)

__device__ __forceinline__ uint32_t smem_u32(const void* p) {
    uint32_t a;
    asm("{ .reg .u64 t; cvta.to.shared.u64 t, %1; cvt.u32.u64 %0, t; }"
        : "=r"(a) : "l"(p));
    return a;
}

#define CP_ASYNC(dst, src, sz) \
    asm volatile("cp.async.ca.shared.global [%0], [%1], 16, %2;" \
                 :: "r"(dst), "l"(src), "r"(sz))
#define CP_COMMIT()  asm volatile("cp.async.commit_group;")
#define CP_WAIT(N)   asm volatile("cp.async.wait_group %0;" :: "n"(N))

#define LDSM_X4(r0, r1, r2, r3, addr) \
    asm volatile("ldmatrix.sync.aligned.m8n8.x4.shared.b16 {%0,%1,%2,%3}, [%4];" \
                 : "=r"(r0), "=r"(r1), "=r"(r2), "=r"(r3) : "r"(addr))

__device__ __forceinline__ void mma_f16(float* d, uint32_t a0, uint32_t a1,
                                        uint32_t a2, uint32_t a3,
                                        uint32_t b0, uint32_t b1) {
    asm volatile(
        "mma.sync.aligned.m16n8k16.row.col.f32.f16.f16.f32 "
        "{%0,%1,%2,%3}, {%4,%5,%6,%7}, {%8,%9}, {%0,%1,%2,%3};"
        : "+f"(d[0]), "+f"(d[1]), "+f"(d[2]), "+f"(d[3])
        : "r"(a0), "r"(a1), "r"(a2), "r"(a3), "r"(b0), "r"(b1));
}

__global__ void __launch_bounds__(256)
k_gemm_h() {
    extern __shared__ char smem[];
    const int tid  = threadIdx.x;
    const int warp = tid >> 5;
    const int lane = tid & 31;
    const int bm = blockIdx.y * BM;
    const int bn = blockIdx.x * BN;
    const int wm = (warp >> 2) * 64;
    const int wn = (warp & 3) * 32;
    const int g  = lane >> 2;
    const int tg = lane & 3;

    const uint32_t sb = smem_u32(smem);
    const int lrow = tid >> 1;
    const int lpart = tid & 1;

    const int lm_row = lane & 15;
    const int lm_k   = (lane >> 4) * 8;
    const int bl_row = lane & 7;
    const int bl_sel = (lane >> 3) & 1;
    const int bl_nt  = (lane >> 4) & 1;

    const __half* Xh = (const __half*)g_xh;
    const __half* Wh = (const __half*)g_wh;

    float acc[4][4][4];
#pragma unroll
    for (int i = 0; i < 4; i++)
#pragma unroll
        for (int j = 0; j < 4; j++)
#pragma unroll
            for (int k = 0; k < 4; k++) acc[i][j][k] = 0.f;

    auto issue = [&](int kc, int buf) {
        const int k0 = kc * 32;
        const uint32_t abase = sb + buf * BUFH;
        const uint32_t bbase = abase + AH_BYTES;
        {
            int r = bm + lrow;
            uint32_t dst = abase + lrow * (PADH * 2) + lpart * 32;
            const __half* src = &Xh[(size_t)r * DIM + k0 + lpart * 16];
            int ok = (r < N_NODES) ? 16 : 0;
            CP_ASYNC(dst,      src,     ok);
            CP_ASYNC(dst + 16, src + 8, ok);
        }
        {
            uint32_t dst = bbase + lrow * (PADH * 2) + lpart * 32;
            const __half* src = &Wh[(size_t)(bn + lrow) * DIM + k0 + lpart * 16];
            CP_ASYNC(dst,      src,     16);
            CP_ASYNC(dst + 16, src + 8, 16);
        }
        CP_COMMIT();
    };

    issue(0, 0);

    for (int kc = 0; kc < DIM / 32; kc++) {
        if (kc + 1 < DIM / 32) {
            issue(kc + 1, (kc + 1) & 1);
            CP_WAIT(1);
        } else {
            CP_WAIT(0);
        }
        __syncthreads();
        const uint32_t abuf = sb + (kc & 1) * BUFH;
        const uint32_t bbuf = abuf + AH_BYTES;
#pragma unroll
        for (int ks = 0; ks < 2; ks++) {
            const int kb = ks * 16;
            uint32_t a[4][4], b[4][2];
#pragma unroll
            for (int mt = 0; mt < 4; mt++) {
                uint32_t addr = abuf +
                    ((wm + mt * 16 + lm_row) * PADH + kb + lm_k) * 2;
                LDSM_X4(a[mt][0], a[mt][1], a[mt][2], a[mt][3], addr);
            }
#pragma unroll
            for (int np = 0; np < 2; np++) {
                int n0 = wn + (2 * np + bl_nt) * 8 + bl_row;
                uint32_t addr = bbuf + (n0 * PADH + kb + bl_sel * 8) * 2;
                LDSM_X4(b[2 * np][0], b[2 * np][1],
                        b[2 * np + 1][0], b[2 * np + 1][1], addr);
            }
#pragma unroll
            for (int mt = 0; mt < 4; mt++)
#pragma unroll
                for (int nt = 0; nt < 4; nt++)
                    mma_f16(acc[mt][nt], a[mt][0], a[mt][1], a[mt][2], a[mt][3],
                            b[nt][0], b[nt][1]);
        }
        __syncthreads();
    }

#pragma unroll
    for (int mt = 0; mt < 4; mt++) {
#pragma unroll
        for (int nt = 0; nt < 4; nt++) {
            int row = bm + wm + mt * 16 + g;
            int col = bn + wn + nt * 8 + 2 * tg;
            if (row < N_NODES)
                g_yh[((size_t)row * DIM + col) / 2] =
                    __floats2half2_rn(acc[mt][nt][0], acc[mt][nt][1]);
            if (row + 8 < N_NODES)
                g_yh[((size_t)(row + 8) * DIM + col) / 2] =
                    __floats2half2_rn(acc[mt][nt][2], acc[mt][nt][3]);
        }
    }
}

// ---------------- SpMM: g_y2h[r] = sum_e val * yh[col] (block per row) ----------------
__global__ __launch_bounds__(128) void k_spmm() {
    int row = blockIdx.x;
    int t = threadIdx.x;
    int s = g_start[row];
    int e = g_start[row + 1];
    int h2off = t * 2;
    float4 acc0 = make_float4(0.f, 0.f, 0.f, 0.f);
    float4 acc1 = make_float4(0.f, 0.f, 0.f, 0.f);
    float4 acc2 = make_float4(0.f, 0.f, 0.f, 0.f);
    float4 acc3 = make_float4(0.f, 0.f, 0.f, 0.f);
    int i = s;
    for (; i + 3 < e; i += 4) {
        int2 e0 = __ldg(&g_edges[i]);
        int2 e1 = __ldg(&g_edges[i + 1]);
        int2 e2 = __ldg(&g_edges[i + 2]);
        int2 e3 = __ldg(&g_edges[i + 3]);
        const __half2* p0 = &g_yh[(size_t)e0.x * H2ROW + h2off];
        const __half2* p1 = &g_yh[(size_t)e1.x * H2ROW + h2off];
        const __half2* p2 = &g_yh[(size_t)e2.x * H2ROW + h2off];
        const __half2* p3 = &g_yh[(size_t)e3.x * H2ROW + h2off];
        float v0 = __int_as_float(e0.y), v1 = __int_as_float(e1.y);
        float v2 = __int_as_float(e2.y), v3 = __int_as_float(e3.y);
        float2 a0 = __half22float2(p0[0]), a1 = __half22float2(p0[1]);
        float2 b0 = __half22float2(p1[0]), b1 = __half22float2(p1[1]);
        float2 c0 = __half22float2(p2[0]), c1 = __half22float2(p2[1]);
        float2 d0 = __half22float2(p3[0]), d1 = __half22float2(p3[1]);
        acc0.x += v0 * a0.x; acc0.y += v0 * a0.y; acc0.z += v0 * a1.x; acc0.w += v0 * a1.y;
        acc1.x += v1 * b0.x; acc1.y += v1 * b0.y; acc1.z += v1 * b1.x; acc1.w += v1 * b1.y;
        acc2.x += v2 * c0.x; acc2.y += v2 * c0.y; acc2.z += v2 * c1.x; acc2.w += v2 * c1.y;
        acc3.x += v3 * d0.x; acc3.y += v3 * d0.y; acc3.z += v3 * d1.x; acc3.w += v3 * d1.y;
    }
    for (; i < e; i++) {
        int2 e0 = __ldg(&g_edges[i]);
        float v0 = __int_as_float(e0.y);
        const __half2* p0 = &g_yh[(size_t)e0.x * H2ROW + h2off];
        float2 a0 = __half22float2(p0[0]), a1 = __half22float2(p0[1]);
        acc0.x += v0 * a0.x; acc0.y += v0 * a0.y; acc0.z += v0 * a1.x; acc0.w += v0 * a1.y;
    }
    acc0.x += acc1.x + acc2.x + acc3.x;
    acc0.y += acc1.y + acc2.y + acc3.y;
    acc0.z += acc1.z + acc2.z + acc3.z;
    acc0.w += acc1.w + acc2.w + acc3.w;
    g_y2h[(size_t)row * H2ROW + h2off]     = __floats2half2_rn(acc0.x, acc0.y);
    g_y2h[(size_t)row * H2ROW + h2off + 1] = __floats2half2_rn(acc0.z, acc0.w);
}

// ------- stats: column sums + sum of squares; LAST block computes mu/alpha -------
__global__ __launch_bounds__(128) void k_reduce(const float* __restrict__ scale) {
    __shared__ float red[128];
    int rows_per = (N_NODES + RED_BLOCKS - 1) / RED_BLOCKS;
    int r0 = blockIdx.x * rows_per;
    int r1 = min(r0 + rows_per, N_NODES);
    int t = threadIdx.x;
    float4 acc = make_float4(0.f, 0.f, 0.f, 0.f);
    float sq = 0.f;
    for (int r = r0; r < r1; r++) {
        const __half2* p = &g_y2h[(size_t)r * H2ROW + t * 2];
        float2 a = __half22float2(p[0]);
        float2 b = __half22float2(p[1]);
        acc.x += a.x; acc.y += a.y; acc.z += b.x; acc.w += b.y;
        sq += a.x * a.x + a.y * a.y + b.x * b.x + b.y * b.y;
    }
    atomicAdd(&g_colsum[t * 4 + 0], acc.x);
    atomicAdd(&g_colsum[t * 4 + 1], acc.y);
    atomicAdd(&g_colsum[t * 4 + 2], acc.z);
    atomicAdd(&g_colsum[t * 4 + 3], acc.w);
#pragma unroll
    for (int off = 16; off; off >>= 1)
        sq += __shfl_xor_sync(0xffffffffu, sq, off);
    if ((t & 31) == 0) atomicAdd(&g_stats[0], sq);

    __threadfence();
    __syncthreads();
    __shared__ int is_last;
    if (t == 0) is_last = (atomicAdd(&g_done, 1) == RED_BLOCKS - 1);
    __syncthreads();
    if (!is_last) return;

    float part = 0.f;
#pragma unroll
    for (int j = 0; j < 4; j++) {
        int c = t * 4 + j;
        float cs = g_colsum[c];
        float mu = cs * (1.0f / N_NODES);
        g_colsum[c] = mu;
        part += cs * mu;
    }
    red[t] = part;
    __syncthreads();
    for (int off = 64; off; off >>= 1) {
        if (t < off) red[t] += red[t + off];
        __syncthreads();
    }
    if (t == 0) {
        float msq = (g_stats[0] - red[0]) * (1.0f / N_NODES);
        g_stats[1] = rsqrtf(msq) * (1.0f + scale[0]) * 22.627416997969522f;
    }
}

// -------- fused center/scale/relu/residual; 2 float4-groups per thread --------
#define NF4 (N_NODES * DIM / 4)                   // 6.4M float4 groups
__global__ __launch_bounds__(256) void k_final(float* __restrict__ Out) {
    int base = blockIdx.x * 512 + threadIdx.x;
    float alpha = g_stats[1];
#pragma unroll
    for (int rep = 0; rep < 2; rep++) {
        int i = base + rep * 256;
        if (i >= NF4) return;
        int d4 = (i & (DIM / 4 - 1)) * 4;
        float4 mu = *(const float4*)&g_colsum[d4];
        const __half2* py = &g_y2h[i * 2];
        const __half2* px = &g_xh[i * 2];
        float2 y01 = __half22float2(py[0]);
        float2 y23 = __half22float2(py[1]);
        float2 x01 = __half22float2(px[0]);
        float2 x23 = __half22float2(px[1]);
        float4 o;
        o.x = fmaxf((y01.x - mu.x) * alpha, 0.f) + x01.x;
        o.y = fmaxf((y01.y - mu.y) * alpha, 0.f) + x01.y;
        o.z = fmaxf((y23.x - mu.z) * alpha, 0.f) + x23.x;
        o.w = fmaxf((y23.y - mu.w) * alpha, 0.f) + x23.y;
        *(float4*)&Out[i * 4] = o;
    }
}

extern "C" void kernel_launch(void* const* d_in, const int* in_sizes, int n_in,
                              void* d_out, int out_size) {
    const float* x     = (const float*)d_in[0];
    const int*   rows  = (const int*)  d_in[1];
    const int*   cols  = (const int*)  d_in[2];
    const float* vals  = (const float*)d_in[3];
    const float* W     = (const float*)d_in[4];
    const float* scale = (const float*)d_in[5];
    float* out = (float*)d_out;

    // Streams/events created AND destroyed within this call (branches joined
    // before return; driver defers handle teardown) so no device memory
    // outlives the run.
    cudaStream_t s2, s3;
    cudaStreamCreate(&s2);
    cudaStreamCreate(&s3);
    cudaEvent_t eFork, eJ2, eJ3;
    cudaEventCreateWithFlags(&eFork, cudaEventDisableTiming);
    cudaEventCreateWithFlags(&eJ2, cudaEventDisableTiming);
    cudaEventCreateWithFlags(&eJ3, cudaEventDisableTiming);

    void* cntp = nullptr;
    cudaGetSymbolAddress(&cntp, g_cnt);

    cudaEventRecord(eFork, 0);
    cudaStreamWaitEvent(s2, eFork, 0);
    cudaStreamWaitEvent(s3, eFork, 0);

    // branch B (s2): CSR build
    cudaMemsetAsync(cntp, 0, N_NODES * sizeof(int), s2);
    k_hist<<<(N_EDGES + 255) / 256, 256, 0, s2>>>(rows);
    k_scan<<<1, 1024, 0, s2>>>();
    k_scatter<<<(N_EDGES + 255) / 256, 256, 0, s2>>>(rows, cols, vals);
    cudaEventRecord(eJ2, s2);

    // branch A (s3): dense path
    k_cvt<<<(NX4 + NW4 + 255) / 256, 256, 0, s3>>>(x, W);
    k_gemm_h<<<dim3(DIM / BN, (N_NODES + BM - 1) / BM), 256, GEMM_SMEM, s3>>>();
    cudaEventRecord(eJ3, s3);

    cudaStreamWaitEvent(0, eJ2, 0);
    cudaStreamWaitEvent(0, eJ3, 0);

    k_spmm<<<N_NODES, 128>>>();
    k_reduce<<<RED_BLOCKS, 128>>>(scale);
    k_final<<<(NF4 + 511) / 512, 256>>>(out);

    // release per-call resources so device memory returns to baseline
    cudaEventDestroy(eFork);
    cudaEventDestroy(eJ2);
    cudaEventDestroy(eJ3);
    cudaStreamDestroy(s2);
    cudaStreamDestroy(s3);
}

// round 16
// speedup vs baseline: 1.0346x; 1.0346x over previous
#include <cuda_runtime.h>
#include <cuda_fp16.h>
#include <cstdint>

#define N_NODES 50000
#define DIM     512
#define N_EDGES 1600000
#define H2ROW   (DIM / 2)
#define RED_BLOCKS 512

// ---- scratch (no allocations allowed -> __device__ globals) ----
__device__ __half2 g_yh[N_NODES * DIM / 2];  // x @ W^T in fp16 (SpMM gather source)
__device__ __half2 g_xh[N_NODES * DIM / 2];  // X in fp16 (GEMM A + residual source)
__device__ __half2 g_y2h[N_NODES * DIM / 2]; // SpMM output in fp16
__device__ __half2 g_wh[DIM * DIM / 2];      // W in fp16 (GEMM B)
__device__ int   g_cnt[N_NODES];
__device__ int   g_start[N_NODES + 1];
__device__ int   g_cursor[N_NODES];
__device__ int2  g_edges[N_EDGES];           // packed (col, val_bits), row-sorted
__device__ float g_colsum[DIM];              // later overwritten with mu[]
__device__ float g_stats[2];                 // [0]=sum of squares, [1]=alpha
__device__ int   g_done;                     // last-block counter for fused finalize

// ---------------- CSR build ----------------
__global__ void k_hist(const int* __restrict__ rows) {
    int i = blockIdx.x * blockDim.x + threadIdx.x;
    if (i < N_EDGES) atomicAdd(&g_cnt[rows[i]], 1);
}

__global__ void k_scan() {
    __shared__ int sm[1024];
    int t = threadIdx.x;
    if (t < DIM) g_colsum[t] = 0.f;
    if (t == 0)  { g_stats[0] = 0.f; g_done = 0; }
    const int CH = (N_NODES + 1023) / 1024;
    int lo = t * CH;
    int hi = min(lo + CH, N_NODES);
    int sum = 0;
    for (int i = lo; i < hi; i++) sum += g_cnt[i];
    sm[t] = sum;
    __syncthreads();
    for (int off = 1; off < 1024; off <<= 1) {
        int v = (t >= off) ? sm[t - off] : 0;
        __syncthreads();
        sm[t] += v;
        __syncthreads();
    }
    int run = sm[t] - sum;
    for (int i = lo; i < hi; i++) {
        g_start[i]  = run;
        g_cursor[i] = run;
        run += g_cnt[i];
    }
    if (t == 1023) g_start[N_NODES] = sm[1023];
}

__global__ void k_scatter(const int* __restrict__ rows,
                          const int* __restrict__ cols,
                          const float* __restrict__ vals) {
    int i = blockIdx.x * blockDim.x + threadIdx.x;
    if (i < N_EDGES) {
        int r = rows[i];
        int p = atomicAdd(&g_cursor[r], 1);
        g_edges[p] = make_int2(cols[i], __float_as_int(vals[i]));
    }
}

// ---------------- fp32 -> fp16 conversion of X and W ----------------
#define NX4 (N_NODES * DIM / 4)
#define NW4 (DIM * DIM / 4)
__global__ __launch_bounds__(256) void k_cvt(const float* __restrict__ X,
                                             const float* __restrict__ W) {
    int i = blockIdx.x * blockDim.x + threadIdx.x;
    if (i < NX4) {
        float4 v = *(const float4*)&X[i * 4];
        g_xh[i * 2]     = __floats2half2_rn(v.x, v.y);
        g_xh[i * 2 + 1] = __floats2half2_rn(v.z, v.w);
    } else if (i < NX4 + NW4) {
        int j = i - NX4;
        float4 v = *(const float4*)&W[j * 4];
        g_wh[j * 2]     = __floats2half2_rn(v.x, v.y);
        g_wh[j * 2 + 1] = __floats2half2_rn(v.z, v.w);
    }
}

// ====== GEMM: g_yh = X @ W^T via mma.sync f16 + ldmatrix (2-stage, .ca) ======
#define BM 128
#define BN 128
#define PADH 40
#define AH_BYTES (128 * PADH * 2)
#define BUFH (2 * AH_BYTES)
#define GEMM_SMEM (2 * BUFH)

__device__ __forceinline__ uint32_t smem_u32(const void* p) {
    uint32_t a;
    asm("{ .reg .u64 t; cvta.to.shared.u64 t, %1; cvt.u32.u64 %0, t; }"
        : "=r"(a) : "l"(p));
    return a;
}

#define CP_ASYNC(dst, src, sz) \
    asm volatile("cp.async.ca.shared.global [%0], [%1], 16, %2;" \
                 :: "r"(dst), "l"(src), "r"(sz))
#define CP_COMMIT()  asm volatile("cp.async.commit_group;")
#define CP_WAIT(N)   asm volatile("cp.async.wait_group %0;" :: "n"(N))

#define LDSM_X4(r0, r1, r2, r3, addr) \
    asm volatile("ldmatrix.sync.aligned.m8n8.x4.shared.b16 {%0,%1,%2,%3}, [%4];" \
                 : "=r"(r0), "=r"(r1), "=r"(r2), "=r"(r3) : "r"(addr))

__device__ __forceinline__ void mma_f16(float* d, uint32_t a0, uint32_t a1,
                                        uint32_t a2, uint32_t a3,
                                        uint32_t b0, uint32_t b1) {
    asm volatile(
        "mma.sync.aligned.m16n8k16.row.col.f32.f16.f16.f32 "
        "{%0,%1,%2,%3}, {%4,%5,%6,%7}, {%8,%9}, {%0,%1,%2,%3};"
        : "+f"(d[0]), "+f"(d[1]), "+f"(d[2]), "+f"(d[3])
        : "r"(a0), "r"(a1), "r"(a2), "r"(a3), "r"(b0), "r"(b1));
}

__global__ void __launch_bounds__(256)
k_gemm_h() {
    extern __shared__ char smem[];
    const int tid  = threadIdx.x;
    const int warp = tid >> 5;
    const int lane = tid & 31;
    const int bm = blockIdx.y * BM;
    const int bn = blockIdx.x * BN;
    const int wm = (warp >> 2) * 64;
    const int wn = (warp & 3) * 32;
    const int g  = lane >> 2;
    const int tg = lane & 3;

    const uint32_t sb = smem_u32(smem);
    const int lrow = tid >> 1;
    const int lpart = tid & 1;

    const int lm_row = lane & 15;
    const int lm_k   = (lane >> 4) * 8;
    const int bl_row = lane & 7;
    const int bl_sel = (lane >> 3) & 1;
    const int bl_nt  = (lane >> 4) & 1;

    const __half* Xh = (const __half*)g_xh;
    const __half* Wh = (const __half*)g_wh;

    float acc[4][4][4];
#pragma unroll
    for (int i = 0; i < 4; i++)
#pragma unroll
        for (int j = 0; j < 4; j++)
#pragma unroll
            for (int k = 0; k < 4; k++) acc[i][j][k] = 0.f;

    auto issue = [&](int kc, int buf) {
        const int k0 = kc * 32;
        const uint32_t abase = sb + buf * BUFH;
        const uint32_t bbase = abase + AH_BYTES;
        {
            int r = bm + lrow;
            uint32_t dst = abase + lrow * (PADH * 2) + lpart * 32;
            const __half* src = &Xh[(size_t)r * DIM + k0 + lpart * 16];
            int ok = (r < N_NODES) ? 16 : 0;
            CP_ASYNC(dst,      src,     ok);
            CP_ASYNC(dst + 16, src + 8, ok);
        }
        {
            uint32_t dst = bbase + lrow * (PADH * 2) + lpart * 32;
            const __half* src = &Wh[(size_t)(bn + lrow) * DIM + k0 + lpart * 16];
            CP_ASYNC(dst,      src,     16);
            CP_ASYNC(dst + 16, src + 8, 16);
        }
        CP_COMMIT();
    };

    issue(0, 0);

    for (int kc = 0; kc < DIM / 32; kc++) {
        if (kc + 1 < DIM / 32) {
            issue(kc + 1, (kc + 1) & 1);
            CP_WAIT(1);
        } else {
            CP_WAIT(0);
        }
        __syncthreads();
        const uint32_t abuf = sb + (kc & 1) * BUFH;
        const uint32_t bbuf = abuf + AH_BYTES;
#pragma unroll
        for (int ks = 0; ks < 2; ks++) {
            const int kb = ks * 16;
            uint32_t a[4][4], b[4][2];
#pragma unroll
            for (int mt = 0; mt < 4; mt++) {
                uint32_t addr = abuf +
                    ((wm + mt * 16 + lm_row) * PADH + kb + lm_k) * 2;
                LDSM_X4(a[mt][0], a[mt][1], a[mt][2], a[mt][3], addr);
            }
#pragma unroll
            for (int np = 0; np < 2; np++) {
                int n0 = wn + (2 * np + bl_nt) * 8 + bl_row;
                uint32_t addr = bbuf + (n0 * PADH + kb + bl_sel * 8) * 2;
                LDSM_X4(b[2 * np][0], b[2 * np][1],
                        b[2 * np + 1][0], b[2 * np + 1][1], addr);
            }
#pragma unroll
            for (int mt = 0; mt < 4; mt++)
#pragma unroll
                for (int nt = 0; nt < 4; nt++)
                    mma_f16(acc[mt][nt], a[mt][0], a[mt][1], a[mt][2], a[mt][3],
                            b[nt][0], b[nt][1]);
        }
        __syncthreads();
    }

#pragma unroll
    for (int mt = 0; mt < 4; mt++) {
#pragma unroll
        for (int nt = 0; nt < 4; nt++) {
            int row = bm + wm + mt * 16 + g;
            int col = bn + wn + nt * 8 + 2 * tg;
            if (row < N_NODES)
                g_yh[((size_t)row * DIM + col) / 2] =
                    __floats2half2_rn(acc[mt][nt][0], acc[mt][nt][1]);
            if (row + 8 < N_NODES)
                g_yh[((size_t)(row + 8) * DIM + col) / 2] =
                    __floats2half2_rn(acc[mt][nt][2], acc[mt][nt][3]);
        }
    }
}

// ---------------- SpMM: g_y2h[r] = sum_e val * yh[col] (block per row) ----------------
__global__ __launch_bounds__(128) void k_spmm() {
    int row = blockIdx.x;
    int t = threadIdx.x;
    int s = g_start[row];
    int e = g_start[row + 1];
    int h2off = t * 2;
    float4 acc0 = make_float4(0.f, 0.f, 0.f, 0.f);
    float4 acc1 = make_float4(0.f, 0.f, 0.f, 0.f);
    float4 acc2 = make_float4(0.f, 0.f, 0.f, 0.f);
    float4 acc3 = make_float4(0.f, 0.f, 0.f, 0.f);
    int i = s;
    for (; i + 3 < e; i += 4) {
        int2 e0 = __ldg(&g_edges[i]);
        int2 e1 = __ldg(&g_edges[i + 1]);
        int2 e2 = __ldg(&g_edges[i + 2]);
        int2 e3 = __ldg(&g_edges[i + 3]);
        const __half2* p0 = &g_yh[(size_t)e0.x * H2ROW + h2off];
        const __half2* p1 = &g_yh[(size_t)e1.x * H2ROW + h2off];
        const __half2* p2 = &g_yh[(size_t)e2.x * H2ROW + h2off];
        const __half2* p3 = &g_yh[(size_t)e3.x * H2ROW + h2off];
        float v0 = __int_as_float(e0.y), v1 = __int_as_float(e1.y);
        float v2 = __int_as_float(e2.y), v3 = __int_as_float(e3.y);
        float2 a0 = __half22float2(p0[0]), a1 = __half22float2(p0[1]);
        float2 b0 = __half22float2(p1[0]), b1 = __half22float2(p1[1]);
        float2 c0 = __half22float2(p2[0]), c1 = __half22float2(p2[1]);
        float2 d0 = __half22float2(p3[0]), d1 = __half22float2(p3[1]);
        acc0.x += v0 * a0.x; acc0.y += v0 * a0.y; acc0.z += v0 * a1.x; acc0.w += v0 * a1.y;
        acc1.x += v1 * b0.x; acc1.y += v1 * b0.y; acc1.z += v1 * b1.x; acc1.w += v1 * b1.y;
        acc2.x += v2 * c0.x; acc2.y += v2 * c0.y; acc2.z += v2 * c1.x; acc2.w += v2 * c1.y;
        acc3.x += v3 * d0.x; acc3.y += v3 * d0.y; acc3.z += v3 * d1.x; acc3.w += v3 * d1.y;
    }
    for (; i < e; i++) {
        int2 e0 = __ldg(&g_edges[i]);
        float v0 = __int_as_float(e0.y);
        const __half2* p0 = &g_yh[(size_t)e0.x * H2ROW + h2off];
        float2 a0 = __half22float2(p0[0]), a1 = __half22float2(p0[1]);
        acc0.x += v0 * a0.x; acc0.y += v0 * a0.y; acc0.z += v0 * a1.x; acc0.w += v0 * a1.y;
    }
    acc0.x += acc1.x + acc2.x + acc3.x;
    acc0.y += acc1.y + acc2.y + acc3.y;
    acc0.z += acc1.z + acc2.z + acc3.z;
    acc0.w += acc1.w + acc2.w + acc3.w;
    g_y2h[(size_t)row * H2ROW + h2off]     = __floats2half2_rn(acc0.x, acc0.y);
    g_y2h[(size_t)row * H2ROW + h2off + 1] = __floats2half2_rn(acc0.z, acc0.w);
}

// ------- stats: column sums + sum of squares; LAST block computes mu/alpha -------
__global__ __launch_bounds__(128) void k_reduce(const float* __restrict__ scale) {
    __shared__ float red[128];
    int rows_per = (N_NODES + RED_BLOCKS - 1) / RED_BLOCKS;
    int r0 = blockIdx.x * rows_per;
    int r1 = min(r0 + rows_per, N_NODES);
    int t = threadIdx.x;
    float4 acc = make_float4(0.f, 0.f, 0.f, 0.f);
    float sq = 0.f;
    for (int r = r0; r < r1; r++) {
        const __half2* p = &g_y2h[(size_t)r * H2ROW + t * 2];
        float2 a = __half22float2(p[0]);
        float2 b = __half22float2(p[1]);
        acc.x += a.x; acc.y += a.y; acc.z += b.x; acc.w += b.y;
        sq += a.x * a.x + a.y * a.y + b.x * b.x + b.y * b.y;
    }
    atomicAdd(&g_colsum[t * 4 + 0], acc.x);
    atomicAdd(&g_colsum[t * 4 + 1], acc.y);
    atomicAdd(&g_colsum[t * 4 + 2], acc.z);
    atomicAdd(&g_colsum[t * 4 + 3], acc.w);
#pragma unroll
    for (int off = 16; off; off >>= 1)
        sq += __shfl_xor_sync(0xffffffffu, sq, off);
    if ((t & 31) == 0) atomicAdd(&g_stats[0], sq);

    __threadfence();
    __syncthreads();
    __shared__ int is_last;
    if (t == 0) is_last = (atomicAdd(&g_done, 1) == RED_BLOCKS - 1);
    __syncthreads();
    if (!is_last) return;

    float part = 0.f;
#pragma unroll
    for (int j = 0; j < 4; j++) {
        int c = t * 4 + j;
        float cs = g_colsum[c];
        float mu = cs * (1.0f / N_NODES);
        g_colsum[c] = mu;
        part += cs * mu;
    }
    red[t] = part;
    __syncthreads();
    for (int off = 64; off; off >>= 1) {
        if (t < off) red[t] += red[t + off];
        __syncthreads();
    }
    if (t == 0) {
        float msq = (g_stats[0] - red[0]) * (1.0f / N_NODES);
        g_stats[1] = rsqrtf(msq) * (1.0f + scale[0]) * 22.627416997969522f;
    }
}

// ---------------- fused center/scale/relu/residual (fp16 X residual) ----------------
__global__ __launch_bounds__(256) void k_final(float* __restrict__ Out) {
    int i = blockIdx.x * blockDim.x + threadIdx.x;
    if (i >= N_NODES * DIM / 4) return;
    float alpha = g_stats[1];
    int d4 = (i & (DIM / 4 - 1)) * 4;
    float4 mu = *(const float4*)&g_colsum[d4];
    const __half2* py = &g_y2h[i * 2];
    const __half2* px = &g_xh[i * 2];
    float2 y01 = __half22float2(py[0]);
    float2 y23 = __half22float2(py[1]);
    float2 x01 = __half22float2(px[0]);
    float2 x23 = __half22float2(px[1]);
    float4 o;
    o.x = fmaxf((y01.x - mu.x) * alpha, 0.f) + x01.x;
    o.y = fmaxf((y01.y - mu.y) * alpha, 0.f) + x01.y;
    o.z = fmaxf((y23.x - mu.z) * alpha, 0.f) + x23.x;
    o.w = fmaxf((y23.y - mu.w) * alpha, 0.f) + x23.y;
    *(float4*)&Out[i * 4] = o;
}

extern "C" void kernel_launch(void* const* d_in, const int* in_sizes, int n_in,
                              void* d_out, int out_size) {
    const float* x     = (const float*)d_in[0];
    const int*   rows  = (const int*)  d_in[1];
    const int*   cols  = (const int*)  d_in[2];
    const float* vals  = (const float*)d_in[3];
    const float* W     = (const float*)d_in[4];
    const float* scale = (const float*)d_in[5];
    float* out = (float*)d_out;

    // Streams/events created AND destroyed within this call (branches joined
    // before return; driver defers handle teardown) so no device memory
    // outlives the run.
    cudaStream_t s2, s3;
    cudaStreamCreate(&s2);
    cudaStreamCreate(&s3);
    cudaEvent_t eFork, eJ2, eJ3;
    cudaEventCreateWithFlags(&eFork, cudaEventDisableTiming);
    cudaEventCreateWithFlags(&eJ2, cudaEventDisableTiming);
    cudaEventCreateWithFlags(&eJ3, cudaEventDisableTiming);

    void* cntp = nullptr;
    cudaGetSymbolAddress(&cntp, g_cnt);

    cudaEventRecord(eFork, 0);
    cudaStreamWaitEvent(s2, eFork, 0);
    cudaStreamWaitEvent(s3, eFork, 0);

    // branch B (s2): CSR build
    cudaMemsetAsync(cntp, 0, N_NODES * sizeof(int), s2);
    k_hist<<<(N_EDGES + 255) / 256, 256, 0, s2>>>(rows);
    k_scan<<<1, 1024, 0, s2>>>();
    k_scatter<<<(N_EDGES + 255) / 256, 256, 0, s2>>>(rows, cols, vals);
    cudaEventRecord(eJ2, s2);

    // branch A (s3): dense path
    k_cvt<<<(NX4 + NW4 + 255) / 256, 256, 0, s3>>>(x, W);
    k_gemm_h<<<dim3(DIM / BN, (N_NODES + BM - 1) / BM), 256, GEMM_SMEM, s3>>>();
    cudaEventRecord(eJ3, s3);

    cudaStreamWaitEvent(0, eJ2, 0);
    cudaStreamWaitEvent(0, eJ3, 0);

    k_spmm<<<N_NODES, 128>>>();
    k_reduce<<<RED_BLOCKS, 128>>>(scale);
    k_final<<<(N_NODES * DIM / 4 + 255) / 256, 256>>>(out);

    // release per-call resources so device memory returns to baseline
    cudaEventDestroy(eFork);
    cudaEventDestroy(eJ2);
    cudaEventDestroy(eJ3);
    cudaStreamDestroy(s2);
    cudaStreamDestroy(s3);
}

// round 17
// speedup vs baseline: 1.0450x; 1.0101x over previous
#include <cuda_runtime.h>
#include <cuda_fp16.h>
#include <cstdint>

#define N_NODES 50000
#define DIM     512
#define N_EDGES 1600000
#define H2ROW   (DIM / 2)
#define RED_BLOCKS 512

// ---- scratch (no allocations allowed -> __device__ globals) ----
__device__ __half2 g_yh[N_NODES * DIM / 2];  // x @ W^T in fp16 (SpMM gather source)
__device__ __half2 g_xh[N_NODES * DIM / 2];  // X in fp16 (GEMM A + residual source)
__device__ __half2 g_y2h[N_NODES * DIM / 2]; // SpMM output in fp16
__device__ __half2 g_wh[DIM * DIM / 2];      // W in fp16 (GEMM B)
__device__ int   g_cnt[N_NODES];
__device__ int   g_start[N_NODES + 1];
__device__ int   g_cursor[N_NODES];
__device__ int2  g_edges[N_EDGES];           // packed (col, val_bits), row-sorted
__device__ float g_colsum[DIM];              // later overwritten with mu[]
__device__ float g_stats[2];                 // [0]=sum of squares, [1]=alpha
__device__ int   g_done;                     // last-block counter for fused finalize

// ---------------- CSR build ----------------
__global__ void k_hist(const int* __restrict__ rows) {
    int i = blockIdx.x * blockDim.x + threadIdx.x;
    if (i < N_EDGES) atomicAdd(&g_cnt[rows[i]], 1);
}

__global__ void k_scan() {
    __shared__ int sm[1024];
    int t = threadIdx.x;
    if (t < DIM) g_colsum[t] = 0.f;
    if (t == 0)  { g_stats[0] = 0.f; g_done = 0; }
    const int CH = (N_NODES + 1023) / 1024;
    int lo = t * CH;
    int hi = min(lo + CH, N_NODES);
    int sum = 0;
    for (int i = lo; i < hi; i++) sum += g_cnt[i];
    sm[t] = sum;
    __syncthreads();
    for (int off = 1; off < 1024; off <<= 1) {
        int v = (t >= off) ? sm[t - off] : 0;
        __syncthreads();
        sm[t] += v;
        __syncthreads();
    }
    int run = sm[t] - sum;
    for (int i = lo; i < hi; i++) {
        g_start[i]  = run;
        g_cursor[i] = run;
        run += g_cnt[i];
    }
    if (t == 1023) g_start[N_NODES] = sm[1023];
}

__global__ void k_scatter(const int* __restrict__ rows,
                          const int* __restrict__ cols,
                          const float* __restrict__ vals) {
    int i = blockIdx.x * blockDim.x + threadIdx.x;
    if (i < N_EDGES) {
        int r = rows[i];
        int p = atomicAdd(&g_cursor[r], 1);
        g_edges[p] = make_int2(cols[i], __float_as_int(vals[i]));
    }
}

// ---------------- fp32 -> fp16 conversion of X and W ----------------
#define NX4 (N_NODES * DIM / 4)
#define NW4 (DIM * DIM / 4)
__global__ __launch_bounds__(256) void k_cvt(const float* __restrict__ X,
                                             const float* __restrict__ W) {
    int i = blockIdx.x * blockDim.x + threadIdx.x;
    if (i < NX4) {
        float4 v = *(const float4*)&X[i * 4];
        g_xh[i * 2]     = __floats2half2_rn(v.x, v.y);
        g_xh[i * 2 + 1] = __floats2half2_rn(v.z, v.w);
    } else if (i < NX4 + NW4) {
        int j = i - NX4;
        float4 v = *(const float4*)&W[j * 4];
        g_wh[j * 2]     = __floats2half2_rn(v.x, v.y);
        g_wh[j * 2 + 1] = __floats2half2_rn(v.z, v.w);
    }
}

// ====== GEMM: g_yh = X @ W^T via mma.sync f16 + ldmatrix (2-stage, .ca) ======
#define BM 128
#define BN 128
#define PADH 40
#define AH_BYTES (128 * PADH * 2)
#define BUFH (2 * AH_BYTES)
#define GEMM_SMEM (2 * BUFH)

__device__ __forceinline__ uint32_t smem_u32(const void* p) {
    uint32_t a;
    asm("{ .reg .u64 t; cvta.to.shared.u64 t, %1; cvt.u32.u64 %0, t; }"
        : "=r"(a) : "l"(p));
    return a;
}

#define CP_ASYNC(dst, src, sz) \
    asm volatile("cp.async.ca.shared.global [%0], [%1], 16, %2;" \
                 :: "r"(dst), "l"(src), "r"(sz))
#define CP_COMMIT()  asm volatile("cp.async.commit_group;")
#define CP_WAIT(N)   asm volatile("cp.async.wait_group %0;" :: "n"(N))

#define LDSM_X4(r0, r1, r2, r3, addr) \
    asm volatile("ldmatrix.sync.aligned.m8n8.x4.shared.b16 {%0,%1,%2,%3}, [%4];" \
                 : "=r"(r0), "=r"(r1), "=r"(r2), "=r"(r3) : "r"(addr))

__device__ __forceinline__ void mma_f16(float* d, uint32_t a0, uint32_t a1,
                                        uint32_t a2, uint32_t a3,
                                        uint32_t b0, uint32_t b1) {
    asm volatile(
        "mma.sync.aligned.m16n8k16.row.col.f32.f16.f16.f32 "
        "{%0,%1,%2,%3}, {%4,%5,%6,%7}, {%8,%9}, {%0,%1,%2,%3};"
        : "+f"(d[0]), "+f"(d[1]), "+f"(d[2]), "+f"(d[3])
        : "r"(a0), "r"(a1), "r"(a2), "r"(a3), "r"(b0), "r"(b1));
}

__global__ void __launch_bounds__(256)
k_gemm_h() {
    extern __shared__ char smem[];
    const int tid  = threadIdx.x;
    const int warp = tid >> 5;
    const int lane = tid & 31;
    const int bm = blockIdx.y * BM;
    const int bn = blockIdx.x * BN;
    const int wm = (warp >> 2) * 64;
    const int wn = (warp & 3) * 32;
    const int g  = lane >> 2;
    const int tg = lane & 3;

    const uint32_t sb = smem_u32(smem);
    const int lrow = tid >> 1;
    const int lpart = tid & 1;

    const int lm_row = lane & 15;
    const int lm_k   = (lane >> 4) * 8;
    const int bl_row = lane & 7;
    const int bl_sel = (lane >> 3) & 1;
    const int bl_nt  = (lane >> 4) & 1;

    const __half* Xh = (const __half*)g_xh;
    const __half* Wh = (const __half*)g_wh;

    float acc[4][4][4];
#pragma unroll
    for (int i = 0; i < 4; i++)
#pragma unroll
        for (int j = 0; j < 4; j++)
#pragma unroll
            for (int k = 0; k < 4; k++) acc[i][j][k] = 0.f;

    auto issue = [&](int kc, int buf) {
        const int k0 = kc * 32;
        const uint32_t abase = sb + buf * BUFH;
        const uint32_t bbase = abase + AH_BYTES;
        {
            int r = bm + lrow;
            uint32_t dst = abase + lrow * (PADH * 2) + lpart * 32;
            const __half* src = &Xh[(size_t)r * DIM + k0 + lpart * 16];
            int ok = (r < N_NODES) ? 16 : 0;
            CP_ASYNC(dst,      src,     ok);
            CP_ASYNC(dst + 16, src + 8, ok);
        }
        {
            uint32_t dst = bbase + lrow * (PADH * 2) + lpart * 32;
            const __half* src = &Wh[(size_t)(bn + lrow) * DIM + k0 + lpart * 16];
            CP_ASYNC(dst,      src,     16);
            CP_ASYNC(dst + 16, src + 8, 16);
        }
        CP_COMMIT();
    };

    issue(0, 0);

    for (int kc = 0; kc < DIM / 32; kc++) {
        if (kc + 1 < DIM / 32) {
            issue(kc + 1, (kc + 1) & 1);
            CP_WAIT(1);
        } else {
            CP_WAIT(0);
        }
        __syncthreads();
        const uint32_t abuf = sb + (kc & 1) * BUFH;
        const uint32_t bbuf = abuf + AH_BYTES;
#pragma unroll
        for (int ks = 0; ks < 2; ks++) {
            const int kb = ks * 16;
            uint32_t a[4][4], b[4][2];
#pragma unroll
            for (int mt = 0; mt < 4; mt++) {
                uint32_t addr = abuf +
                    ((wm + mt * 16 + lm_row) * PADH + kb + lm_k) * 2;
                LDSM_X4(a[mt][0], a[mt][1], a[mt][2], a[mt][3], addr);
            }
#pragma unroll
            for (int np = 0; np < 2; np++) {
                int n0 = wn + (2 * np + bl_nt) * 8 + bl_row;
                uint32_t addr = bbuf + (n0 * PADH + kb + bl_sel * 8) * 2;
                LDSM_X4(b[2 * np][0], b[2 * np][1],
                        b[2 * np + 1][0], b[2 * np + 1][1], addr);
            }
#pragma unroll
            for (int mt = 0; mt < 4; mt++)
#pragma unroll
                for (int nt = 0; nt < 4; nt++)
                    mma_f16(acc[mt][nt], a[mt][0], a[mt][1], a[mt][2], a[mt][3],
                            b[nt][0], b[nt][1]);
        }
        __syncthreads();
    }

#pragma unroll
    for (int mt = 0; mt < 4; mt++) {
#pragma unroll
        for (int nt = 0; nt < 4; nt++) {
            int row = bm + wm + mt * 16 + g;
            int col = bn + wn + nt * 8 + 2 * tg;
            if (row < N_NODES)
                g_yh[((size_t)row * DIM + col) / 2] =
                    __floats2half2_rn(acc[mt][nt][0], acc[mt][nt][1]);
            if (row + 8 < N_NODES)
                g_yh[((size_t)(row + 8) * DIM + col) / 2] =
                    __floats2half2_rn(acc[mt][nt][2], acc[mt][nt][3]);
        }
    }
}

// ---------------- SpMM: g_y2h[r] = sum_e val * yh[col] (block per row) ----------------
__global__ __launch_bounds__(128) void k_spmm() {
    int row = blockIdx.x;
    int t = threadIdx.x;
    int s = g_start[row];
    int e = g_start[row + 1];
    int h2off = t * 2;
    float4 acc0 = make_float4(0.f, 0.f, 0.f, 0.f);
    float4 acc1 = make_float4(0.f, 0.f, 0.f, 0.f);
    float4 acc2 = make_float4(0.f, 0.f, 0.f, 0.f);
    float4 acc3 = make_float4(0.f, 0.f, 0.f, 0.f);
    int i = s;
    for (; i + 3 < e; i += 4) {
        int2 e0 = __ldg(&g_edges[i]);
        int2 e1 = __ldg(&g_edges[i + 1]);
        int2 e2 = __ldg(&g_edges[i + 2]);
        int2 e3 = __ldg(&g_edges[i + 3]);
        const __half2* p0 = &g_yh[(size_t)e0.x * H2ROW + h2off];
        const __half2* p1 = &g_yh[(size_t)e1.x * H2ROW + h2off];
        const __half2* p2 = &g_yh[(size_t)e2.x * H2ROW + h2off];
        const __half2* p3 = &g_yh[(size_t)e3.x * H2ROW + h2off];
        float v0 = __int_as_float(e0.y), v1 = __int_as_float(e1.y);
        float v2 = __int_as_float(e2.y), v3 = __int_as_float(e3.y);
        float2 a0 = __half22float2(p0[0]), a1 = __half22float2(p0[1]);
        float2 b0 = __half22float2(p1[0]), b1 = __half22float2(p1[1]);
        float2 c0 = __half22float2(p2[0]), c1 = __half22float2(p2[1]);
        float2 d0 = __half22float2(p3[0]), d1 = __half22float2(p3[1]);
        acc0.x += v0 * a0.x; acc0.y += v0 * a0.y; acc0.z += v0 * a1.x; acc0.w += v0 * a1.y;
        acc1.x += v1 * b0.x; acc1.y += v1 * b0.y; acc1.z += v1 * b1.x; acc1.w += v1 * b1.y;
        acc2.x += v2 * c0.x; acc2.y += v2 * c0.y; acc2.z += v2 * c1.x; acc2.w += v2 * c1.y;
        acc3.x += v3 * d0.x; acc3.y += v3 * d0.y; acc3.z += v3 * d1.x; acc3.w += v3 * d1.y;
    }
    for (; i < e; i++) {
        int2 e0 = __ldg(&g_edges[i]);
        float v0 = __int_as_float(e0.y);
        const __half2* p0 = &g_yh[(size_t)e0.x * H2ROW + h2off];
        float2 a0 = __half22float2(p0[0]), a1 = __half22float2(p0[1]);
        acc0.x += v0 * a0.x; acc0.y += v0 * a0.y; acc0.z += v0 * a1.x; acc0.w += v0 * a1.y;
    }
    acc0.x += acc1.x + acc2.x + acc3.x;
    acc0.y += acc1.y + acc2.y + acc3.y;
    acc0.z += acc1.z + acc2.z + acc3.z;
    acc0.w += acc1.w + acc2.w + acc3.w;
    g_y2h[(size_t)row * H2ROW + h2off]     = __floats2half2_rn(acc0.x, acc0.y);
    g_y2h[(size_t)row * H2ROW + h2off + 1] = __floats2half2_rn(acc0.z, acc0.w);
}

// ------- stats: column sums + sum of squares; LAST block computes mu/alpha -------
__global__ __launch_bounds__(128) void k_reduce(const float* __restrict__ scale) {
    __shared__ float red[128];
    int rows_per = (N_NODES + RED_BLOCKS - 1) / RED_BLOCKS;
    int r0 = blockIdx.x * rows_per;
    int r1 = min(r0 + rows_per, N_NODES);
    int t = threadIdx.x;
    float4 acc = make_float4(0.f, 0.f, 0.f, 0.f);
    float sq = 0.f;
    for (int r = r0; r < r1; r++) {
        const __half2* p = &g_y2h[(size_t)r * H2ROW + t * 2];
        float2 a = __half22float2(p[0]);
        float2 b = __half22float2(p[1]);
        acc.x += a.x; acc.y += a.y; acc.z += b.x; acc.w += b.y;
        sq += a.x * a.x + a.y * a.y + b.x * b.x + b.y * b.y;
    }
    atomicAdd(&g_colsum[t * 4 + 0], acc.x);
    atomicAdd(&g_colsum[t * 4 + 1], acc.y);
    atomicAdd(&g_colsum[t * 4 + 2], acc.z);
    atomicAdd(&g_colsum[t * 4 + 3], acc.w);
#pragma unroll
    for (int off = 16; off; off >>= 1)
        sq += __shfl_xor_sync(0xffffffffu, sq, off);
    if ((t & 31) == 0) atomicAdd(&g_stats[0], sq);

    __threadfence();
    __syncthreads();
    __shared__ int is_last;
    if (t == 0) is_last = (atomicAdd(&g_done, 1) == RED_BLOCKS - 1);
    __syncthreads();
    if (!is_last) return;

    float part = 0.f;
#pragma unroll
    for (int j = 0; j < 4; j++) {
        int c = t * 4 + j;
        float cs = g_colsum[c];
        float mu = cs * (1.0f / N_NODES);
        g_colsum[c] = mu;
        part += cs * mu;
    }
    red[t] = part;
    __syncthreads();
    for (int off = 64; off; off >>= 1) {
        if (t < off) red[t] += red[t + off];
        __syncthreads();
    }
    if (t == 0) {
        float msq = (g_stats[0] - red[0]) * (1.0f / N_NODES);
        g_stats[1] = rsqrtf(msq) * (1.0f + scale[0]) * 22.627416997969522f;
    }
}

// ---------------- fused center/scale/relu/residual (fp16 X residual) ----------------
__global__ __launch_bounds__(256) void k_final(float* __restrict__ Out) {
    int i = blockIdx.x * blockDim.x + threadIdx.x;
    if (i >= N_NODES * DIM / 4) return;
    float alpha = g_stats[1];
    int d4 = (i & (DIM / 4 - 1)) * 4;
    float4 mu = *(const float4*)&g_colsum[d4];
    const __half2* py = &g_y2h[i * 2];
    const __half2* px = &g_xh[i * 2];
    float2 y01 = __half22float2(py[0]);
    float2 y23 = __half22float2(py[1]);
    float2 x01 = __half22float2(px[0]);
    float2 x23 = __half22float2(px[1]);
    float4 o;
    o.x = fmaxf((y01.x - mu.x) * alpha, 0.f) + x01.x;
    o.y = fmaxf((y01.y - mu.y) * alpha, 0.f) + x01.y;
    o.z = fmaxf((y23.x - mu.z) * alpha, 0.f) + x23.x;
    o.w = fmaxf((y23.y - mu.w) * alpha, 0.f) + x23.y;
    *(float4*)&Out[i * 4] = o;
}

extern "C" void kernel_launch(void* const* d_in, const int* in_sizes, int n_in,
                              void* d_out, int out_size) {
    const float* x     = (const float*)d_in[0];
    const int*   rows  = (const int*)  d_in[1];
    const int*   cols  = (const int*)  d_in[2];
    const float* vals  = (const float*)d_in[3];
    const float* W     = (const float*)d_in[4];
    const float* scale = (const float*)d_in[5];
    float* out = (float*)d_out;

    // Streams/events created AND destroyed within this call (branches joined
    // before return; driver defers handle teardown) so no device memory
    // outlives the run.
    cudaStream_t s2, s3;
    cudaStreamCreate(&s2);
    cudaStreamCreate(&s3);
    cudaEvent_t eFork, eJ2, eJ3;
    cudaEventCreateWithFlags(&eFork, cudaEventDisableTiming);
    cudaEventCreateWithFlags(&eJ2, cudaEventDisableTiming);
    cudaEventCreateWithFlags(&eJ3, cudaEventDisableTiming);

    void* cntp = nullptr;
    cudaGetSymbolAddress(&cntp, g_cnt);

    cudaEventRecord(eFork, 0);
    cudaStreamWaitEvent(s2, eFork, 0);
    cudaStreamWaitEvent(s3, eFork, 0);

    // branch B (s2): CSR build
    cudaMemsetAsync(cntp, 0, N_NODES * sizeof(int), s2);
    k_hist<<<(N_EDGES + 255) / 256, 256, 0, s2>>>(rows);
    k_scan<<<1, 1024, 0, s2>>>();
    k_scatter<<<(N_EDGES + 255) / 256, 256, 0, s2>>>(rows, cols, vals);
    cudaEventRecord(eJ2, s2);

    // branch A (s3): dense path
    k_cvt<<<(NX4 + NW4 + 255) / 256, 256, 0, s3>>>(x, W);
    k_gemm_h<<<dim3(DIM / BN, (N_NODES + BM - 1) / BM), 256, GEMM_SMEM, s3>>>();
    cudaEventRecord(eJ3, s3);

    cudaStreamWaitEvent(0, eJ2, 0);
    cudaStreamWaitEvent(0, eJ3, 0);

    k_spmm<<<N_NODES, 128>>>();
    k_reduce<<<RED_BLOCKS, 128>>>(scale);
    k_final<<<(N_NODES * DIM / 4 + 255) / 256, 256>>>(out);

    // release per-call resources so device memory returns to baseline
    cudaEventDestroy(eFork);
    cudaEventDestroy(eJ2);
    cudaEventDestroy(eJ3);
    cudaStreamDestroy(s2);
    cudaStreamDestroy(s3);
}